// round 1
// baseline (speedup 1.0000x reference)
#include <cuda_runtime.h>
#include <cuda_bf16.h>

#define N_NODES 100000
#define N_EDGES 1200000
#define N_GRAPHS 1000

// ---------------- scratch (device globals; no allocation allowed) ----------
__device__ float g_h0[N_NODES * 32];    // after embed+pre MLP
__device__ float g_agg1[N_NODES * 32];  // edge agg layer 1
__device__ float g_h1[N_NODES * 64];    // after layer 1
__device__ float g_agg2[N_NODES * 64];  // edge agg layer 2
__device__ float g_h2[N_NODES * 64];    // after layer 2
__device__ float g_gsum[N_GRAPHS * 64]; // per-graph sums
__device__ float g_gcnt[N_GRAPHS];      // per-graph counts

// ---------------- K1: embed + pre-linear + relu ----------------------------
__global__ void embed_pre_kernel(const int* __restrict__ x,
                                 const float* __restrict__ shape_emb,
                                 const float* __restrict__ color_emb,
                                 const float* __restrict__ W_pre,
                                 const float* __restrict__ b_pre) {
    __shared__ float sSE[16 * 8];
    __shared__ float sCE[8 * 8];
    __shared__ float sW[32 * 16];
    __shared__ float sB[32];
    for (int idx = threadIdx.x; idx < 128; idx += blockDim.x) sSE[idx] = shape_emb[idx];
    for (int idx = threadIdx.x; idx < 64; idx += blockDim.x)  sCE[idx] = color_emb[idx];
    for (int idx = threadIdx.x; idx < 512; idx += blockDim.x) sW[idx]  = W_pre[idx];
    if (threadIdx.x < 32) sB[threadIdx.x] = b_pre[threadIdx.x];
    __syncthreads();

    int i = blockIdx.x * blockDim.x + threadIdx.x;
    if (i >= N_NODES) return;
    int2 xi = ((const int2*)x)[i];
    float in[16];
#pragma unroll
    for (int k = 0; k < 8; k++) {
        in[k]     = sSE[xi.x * 8 + k];
        in[8 + k] = sCE[xi.y * 8 + k];
    }
    float out[32];
#pragma unroll
    for (int o = 0; o < 32; o++) {
        float acc = sB[o];
#pragma unroll
        for (int k = 0; k < 16; k++) acc += sW[o * 16 + k] * in[k];
        out[o] = fmaxf(acc, 0.0f);
    }
    float4* dst = (float4*)(g_h0 + (long)i * 32);
#pragma unroll
    for (int j = 0; j < 8; j++)
        dst[j] = make_float4(out[j * 4], out[j * 4 + 1], out[j * 4 + 2], out[j * 4 + 3]);
}

// ---------------- K2/K4: edge scatter-add (vector reductions) --------------
// VEC = number of float4 per node row (8 for D=32, 16 for D=64).
template <int VEC, int LOGVEC>
__global__ void edge_agg_kernel(const int* __restrict__ src,
                                const int* __restrict__ dst,
                                const float* __restrict__ hin,
                                float* __restrict__ agg) {
    int t = blockIdx.x * blockDim.x + threadIdx.x;
    int e = t >> LOGVEC;
    int j = t & (VEC - 1);
    if (e >= N_EDGES) return;
    int s = src[e];
    int d = dst[e];
    float4 v = ((const float4*)hin)[(long)s * VEC + j];
    float* p = agg + ((long)d * VEC + j) * 4;
    asm volatile("red.global.add.v4.f32 [%0], {%1,%2,%3,%4};"
                 :: "l"(p), "f"(v.x), "f"(v.y), "f"(v.z), "f"(v.w) : "memory");
}

// ---------------- K3/K5: node update (agg@Wrel^T + b + h@Wroot^T, relu) ----
// 2 nodes per thread, 4 "part" threads per node pair (16 outputs each).
// Weights staged transposed in shared so weight loads are LDS.128.
template <int DIN>
__global__ void node_update_kernel(const float* __restrict__ agg,
                                   const float* __restrict__ hin,
                                   const float* __restrict__ Wrel,
                                   const float* __restrict__ brel,
                                   const float* __restrict__ Wroot,
                                   float* __restrict__ hout) {
    __shared__ float sWrel[DIN * 64];   // [k][o]
    __shared__ float sWroot[DIN * 64];  // [k][o]
    __shared__ float sB[64];
    for (int idx = threadIdx.x; idx < DIN * 64; idx += blockDim.x) {
        int o = idx & 63, k = idx >> 6;
        sWrel[idx]  = Wrel[o * DIN + k];
        sWroot[idx] = Wroot[o * DIN + k];
    }
    if (threadIdx.x < 64) sB[threadIdx.x] = brel[threadIdx.x];
    __syncthreads();

    int t = blockIdx.x * blockDim.x + threadIdx.x;
    int pairIdx = t >> 2;
    int part = t & 3;             // outputs [part*16, part*16+16)
    int n0 = pairIdx * 2;
    if (n0 >= N_NODES) return;    // N_NODES even -> n1 = n0+1 always valid
    int n1 = n0 + 1;

    float acc0[16], acc1[16];
#pragma unroll
    for (int o = 0; o < 16; o++) { acc0[o] = sB[part * 16 + o]; acc1[o] = acc0[o]; }

    const float4* a0 = (const float4*)(agg + (long)n0 * DIN);
    const float4* h0 = (const float4*)(hin + (long)n0 * DIN);
    const float4* a1 = (const float4*)(agg + (long)n1 * DIN);
    const float4* h1 = (const float4*)(hin + (long)n1 * DIN);

#pragma unroll 4
    for (int k4 = 0; k4 < DIN / 4; k4++) {
        float4 av0 = a0[k4], hv0 = h0[k4];
        float4 av1 = a1[k4], hv1 = h1[k4];
        float a0a[4] = {av0.x, av0.y, av0.z, av0.w};
        float h0a[4] = {hv0.x, hv0.y, hv0.z, hv0.w};
        float a1a[4] = {av1.x, av1.y, av1.z, av1.w};
        float h1a[4] = {hv1.x, hv1.y, hv1.z, hv1.w};
#pragma unroll
        for (int kk = 0; kk < 4; kk++) {
            int k = k4 * 4 + kk;
            const float4* wr = (const float4*)(sWrel + k * 64 + part * 16);
            const float4* wo = (const float4*)(sWroot + k * 64 + part * 16);
            float as0 = a0a[kk], hs0 = h0a[kk];
            float as1 = a1a[kk], hs1 = h1a[kk];
#pragma unroll
            for (int j = 0; j < 4; j++) {
                float4 w1 = wr[j];
                float4 w2 = wo[j];
                acc0[j * 4 + 0] += w1.x * as0 + w2.x * hs0;
                acc0[j * 4 + 1] += w1.y * as0 + w2.y * hs0;
                acc0[j * 4 + 2] += w1.z * as0 + w2.z * hs0;
                acc0[j * 4 + 3] += w1.w * as0 + w2.w * hs0;
                acc1[j * 4 + 0] += w1.x * as1 + w2.x * hs1;
                acc1[j * 4 + 1] += w1.y * as1 + w2.y * hs1;
                acc1[j * 4 + 2] += w1.z * as1 + w2.z * hs1;
                acc1[j * 4 + 3] += w1.w * as1 + w2.w * hs1;
            }
        }
    }

    float4* d0 = (float4*)(hout + (long)n0 * 64 + part * 16);
    float4* d1 = (float4*)(hout + (long)n1 * 64 + part * 16);
#pragma unroll
    for (int j = 0; j < 4; j++) {
        d0[j] = make_float4(fmaxf(acc0[j*4+0],0.f), fmaxf(acc0[j*4+1],0.f),
                            fmaxf(acc0[j*4+2],0.f), fmaxf(acc0[j*4+3],0.f));
        d1[j] = make_float4(fmaxf(acc1[j*4+0],0.f), fmaxf(acc1[j*4+1],0.f),
                            fmaxf(acc1[j*4+2],0.f), fmaxf(acc1[j*4+3],0.f));
    }
}

// ---------------- K6: global mean pool (sum + count) -----------------------
__global__ void pool_kernel(const int* __restrict__ batch) {
    int t = blockIdx.x * blockDim.x + threadIdx.x;
    int i = t >> 4;
    int j = t & 15;
    if (i >= N_NODES) return;
    int g = batch[i];
    float4 v = ((const float4*)g_h2)[(long)i * 16 + j];
    float* p = g_gsum + ((long)g * 16 + j) * 4;
    asm volatile("red.global.add.v4.f32 [%0], {%1,%2,%3,%4};"
                 :: "l"(p), "f"(v.x), "f"(v.y), "f"(v.z), "f"(v.w) : "memory");
    if (j == 0) atomicAdd(&g_gcnt[g], 1.0f);
}

// ---------------- K7: classifier -------------------------------------------
__global__ void cls_kernel(const float* __restrict__ W_cls,
                           const float* __restrict__ b_cls,
                           float* __restrict__ out) {
    __shared__ float sp[64];
    int g = blockIdx.x;
    float c = fmaxf(g_gcnt[g], 1.0f);
    sp[threadIdx.x] = g_gsum[(long)g * 64 + threadIdx.x] / c;
    __syncthreads();
    if (threadIdx.x < 10) {
        int o = threadIdx.x;
        float acc = b_cls[o];
#pragma unroll
        for (int k = 0; k < 64; k++) acc += sp[k] * W_cls[o * 64 + k];
        out[(long)g * 10 + o] = acc;
    }
}

// ---------------- launch ----------------------------------------------------
extern "C" void kernel_launch(void* const* d_in, const int* in_sizes, int n_in,
                              void* d_out, int out_size) {
    const int* x     = (const int*)d_in[0];
    const int* edge  = (const int*)d_in[1];
    const int* batch = (const int*)d_in[2];

    // locate shape_emb (the unique size-128 tensor among params)
    int se = -1;
    for (int i = 3; i < n_in; i++) {
        if (in_sizes[i] == 128) { se = i; break; }
    }
    if (se < 0) se = (n_in == 16) ? 4 : 3;

    const float* shape_emb = (const float*)d_in[se + 0];
    const float* color_emb = (const float*)d_in[se + 1];
    const float* W_pre     = (const float*)d_in[se + 2];
    const float* b_pre     = (const float*)d_in[se + 3];
    const float* W_rel1    = (const float*)d_in[se + 4];
    const float* b_rel1    = (const float*)d_in[se + 5];
    const float* W_root1   = (const float*)d_in[se + 6];
    const float* W_rel2    = (const float*)d_in[se + 7];
    const float* b_rel2    = (const float*)d_in[se + 8];
    const float* W_root2   = (const float*)d_in[se + 9];
    const float* W_cls     = (const float*)d_in[se + 10];
    const float* b_cls     = (const float*)d_in[se + 11];

    float* out = (float*)d_out;

    void *p_agg1, *p_agg2, *p_gsum, *p_gcnt, *p_h0, *p_h1, *p_h2;
    cudaGetSymbolAddress(&p_agg1, g_agg1);
    cudaGetSymbolAddress(&p_agg2, g_agg2);
    cudaGetSymbolAddress(&p_gsum, g_gsum);
    cudaGetSymbolAddress(&p_gcnt, g_gcnt);
    cudaGetSymbolAddress(&p_h0, g_h0);
    cudaGetSymbolAddress(&p_h1, g_h1);
    cudaGetSymbolAddress(&p_h2, g_h2);

    cudaMemsetAsync(p_agg1, 0, (size_t)N_NODES * 32 * sizeof(float));
    cudaMemsetAsync(p_agg2, 0, (size_t)N_NODES * 64 * sizeof(float));
    cudaMemsetAsync(p_gsum, 0, (size_t)N_GRAPHS * 64 * sizeof(float));
    cudaMemsetAsync(p_gcnt, 0, (size_t)N_GRAPHS * sizeof(float));

    // K1: embed + pre
    embed_pre_kernel<<<(N_NODES + 255) / 256, 256>>>(x, shape_emb, color_emb, W_pre, b_pre);

    // K2: edge agg layer 1 (D=32, VEC=8)
    {
        int threads = N_EDGES * 8;
        edge_agg_kernel<8, 3><<<(threads + 255) / 256, 256>>>(
            edge, edge + N_EDGES, (const float*)p_h0, (float*)p_agg1);
    }

    // K3: node update layer 1 (DIN=32)
    {
        int threads = (N_NODES / 2) * 4;
        node_update_kernel<32><<<(threads + 255) / 256, 256>>>(
            (const float*)p_agg1, (const float*)p_h0, W_rel1, b_rel1, W_root1, (float*)p_h1);
    }

    // K4: edge agg layer 2 (D=64, VEC=16)
    {
        int threads = N_EDGES * 16;
        edge_agg_kernel<16, 4><<<(threads + 255) / 256, 256>>>(
            edge, edge + N_EDGES, (const float*)p_h1, (float*)p_agg2);
    }

    // K5: node update layer 2 (DIN=64)
    {
        int threads = (N_NODES / 2) * 4;
        node_update_kernel<64><<<(threads + 255) / 256, 256>>>(
            (const float*)p_agg2, (const float*)p_h1, W_rel2, b_rel2, W_root2, (float*)p_h2);
    }

    // K6: pooling
    {
        int threads = N_NODES * 16;
        pool_kernel<<<(threads + 255) / 256, 256>>>(batch);
    }

    // K7: classifier
    cls_kernel<<<N_GRAPHS, 64>>>(W_cls, b_cls, out);

    (void)out_size;
}

// round 2
// speedup vs baseline: 1.0412x; 1.0412x over previous
#include <cuda_runtime.h>
#include <cuda_bf16.h>

#define N_NODES 100000
#define N_EDGES 1200000
#define N_GRAPHS 1000

// ---------------- scratch (device globals; no allocation allowed) ----------
__device__ float g_h0[N_NODES * 32];    // after embed+pre MLP
__device__ float g_agg1[N_NODES * 32];  // edge agg layer 1
__device__ float g_h1[N_NODES * 64];    // after layer 1
__device__ float g_agg2[N_NODES * 64];  // edge agg layer 2
__device__ float g_h2[N_NODES * 64];    // after layer 2
__device__ float g_gsum[N_GRAPHS * 64]; // per-graph sums
__device__ float g_gcnt[N_GRAPHS];      // per-graph counts

// CSR scratch
__device__ int g_deg[N_NODES];
__device__ int g_off[N_NODES + 1];
__device__ int g_cur[N_NODES];
__device__ int g_srcs[N_EDGES];

// ---------------- packed f32x2 helpers (sm_103a) ----------------------------
__device__ __forceinline__ unsigned long long dup_f32(float a) {
    unsigned long long r;
    asm("mov.b64 %0, {%1, %1};" : "=l"(r) : "f"(a));
    return r;
}
__device__ __forceinline__ unsigned long long pack_f32(float lo, float hi) {
    unsigned long long r;
    asm("mov.b64 %0, {%1, %2};" : "=l"(r) : "f"(lo), "f"(hi));
    return r;
}
__device__ __forceinline__ void fma2(unsigned long long& d,
                                     unsigned long long a,
                                     unsigned long long b) {
    asm("fma.rn.f32x2 %0, %1, %2, %0;" : "+l"(d) : "l"(a), "l"(b));
}
__device__ __forceinline__ float2 unpack_f32(unsigned long long v) {
    float lo, hi;
    asm("mov.b64 {%0, %1}, %2;" : "=f"(lo), "=f"(hi) : "l"(v));
    return make_float2(lo, hi);
}

// ---------------- CSR build --------------------------------------------------
__global__ void hist_kernel(const int* __restrict__ dst) {
    int e = blockIdx.x * blockDim.x + threadIdx.x;
    if (e >= N_EDGES) return;
    atomicAdd(&g_deg[dst[e]], 1);
}

__global__ void scan_kernel() {
    __shared__ int ssum[1024];
    const int C = (N_NODES + 1023) >> 10;
    int t = threadIdx.x;
    int lo = t * C;
    int hi = min(lo + C, N_NODES);
    int s = 0;
    for (int i = lo; i < hi; i++) s += g_deg[i];
    ssum[t] = s;
    __syncthreads();
    // Hillis-Steele inclusive scan
    for (int off = 1; off < 1024; off <<= 1) {
        int v = (t >= off) ? ssum[t - off] : 0;
        __syncthreads();
        ssum[t] += v;
        __syncthreads();
    }
    int base = (t == 0) ? 0 : ssum[t - 1];
    for (int i = lo; i < hi; i++) {
        g_off[i] = base;
        base += g_deg[i];
    }
    if (hi >= N_NODES) g_off[N_NODES] = base;
}

__global__ void scatter_kernel(const int* __restrict__ src,
                               const int* __restrict__ dst) {
    int e = blockIdx.x * blockDim.x + threadIdx.x;
    if (e >= N_EDGES) return;
    int d = dst[e];
    int p = atomicAdd(&g_cur[d], 1);
    g_srcs[g_off[d] + p] = src[e];
}

// ---------------- K1: embed + pre-linear + relu ----------------------------
__global__ void embed_pre_kernel(const int* __restrict__ x,
                                 const float* __restrict__ shape_emb,
                                 const float* __restrict__ color_emb,
                                 const float* __restrict__ W_pre,
                                 const float* __restrict__ b_pre) {
    __shared__ float sSE[16 * 8];
    __shared__ float sCE[8 * 8];
    __shared__ float sW[32 * 16];
    __shared__ float sB[32];
    for (int idx = threadIdx.x; idx < 128; idx += blockDim.x) sSE[idx] = shape_emb[idx];
    for (int idx = threadIdx.x; idx < 64; idx += blockDim.x)  sCE[idx] = color_emb[idx];
    for (int idx = threadIdx.x; idx < 512; idx += blockDim.x) sW[idx]  = W_pre[idx];
    if (threadIdx.x < 32) sB[threadIdx.x] = b_pre[threadIdx.x];
    __syncthreads();

    int i = blockIdx.x * blockDim.x + threadIdx.x;
    if (i >= N_NODES) return;
    int2 xi = ((const int2*)x)[i];
    float in[16];
#pragma unroll
    for (int k = 0; k < 8; k++) {
        in[k]     = sSE[xi.x * 8 + k];
        in[8 + k] = sCE[xi.y * 8 + k];
    }
    float out[32];
#pragma unroll
    for (int o = 0; o < 32; o++) {
        float acc = sB[o];
#pragma unroll
        for (int k = 0; k < 16; k++) acc += sW[o * 16 + k] * in[k];
        out[o] = fmaxf(acc, 0.0f);
    }
    float4* dst = (float4*)(g_h0 + (long)i * 32);
#pragma unroll
    for (int j = 0; j < 8; j++)
        dst[j] = make_float4(out[j * 4], out[j * 4 + 1], out[j * 4 + 2], out[j * 4 + 3]);
}

// ---------------- CSR aggregation (no atomics) ------------------------------
// D = node feature width. PARTS = D/16 threads per node, each accumulating
// 16 floats (4 float4) over all incoming edges.
template <int D, int LOGP>
__global__ void csr_agg_kernel(const float* __restrict__ hin,
                               float* __restrict__ agg) {
    constexpr int PARTS = D / 16;
    int t = blockIdx.x * blockDim.x + threadIdx.x;
    int node = t >> LOGP;
    int part = t & (PARTS - 1);
    if (node >= N_NODES) return;
    int lo = g_off[node];
    int hi = g_off[node + 1];

    float4 a0 = make_float4(0.f, 0.f, 0.f, 0.f);
    float4 a1 = a0, a2 = a0, a3 = a0;

    const float4* base = (const float4*)hin + part * 4;
    for (int e = lo; e < hi; e++) {
        int s = g_srcs[e];
        const float4* row = base + (long)s * (D / 4);
        float4 v0 = row[0], v1 = row[1], v2 = row[2], v3 = row[3];
        a0.x += v0.x; a0.y += v0.y; a0.z += v0.z; a0.w += v0.w;
        a1.x += v1.x; a1.y += v1.y; a1.z += v1.z; a1.w += v1.w;
        a2.x += v2.x; a2.y += v2.y; a2.z += v2.z; a2.w += v2.w;
        a3.x += v3.x; a3.y += v3.y; a3.z += v3.z; a3.w += v3.w;
    }
    float4* out = (float4*)agg + (long)node * (D / 4) + part * 4;
    out[0] = a0; out[1] = a1; out[2] = a2; out[3] = a3;
}

// ---------------- node update: agg@Wrel^T + b + h@Wroot^T, relu ------------
// 4 nodes per thread, 2 halves (32 outputs each) per node.
// Accumulators packed as f32x2 (16 pairs per node), weights streamed from
// shared as 64-bit pairs, MACs via fma.rn.f32x2 (2 MACs/issue).
template <int DIN>
__global__ void __launch_bounds__(128)
node_update_kernel(const float* __restrict__ agg,
                   const float* __restrict__ hin,
                   const float* __restrict__ Wrel,
                   const float* __restrict__ brel,
                   const float* __restrict__ Wroot,
                   float* __restrict__ hout) {
    __shared__ float sWrel[DIN * 64];   // [k][o]
    __shared__ float sWroot[DIN * 64];  // [k][o]
    __shared__ float sB[64];
    for (int idx = threadIdx.x; idx < DIN * 64; idx += blockDim.x) {
        int o = idx & 63, k = idx >> 6;
        sWrel[idx]  = Wrel[o * DIN + k];
        sWroot[idx] = Wroot[o * DIN + k];
    }
    for (int idx = threadIdx.x; idx < 64; idx += blockDim.x) sB[idx] = brel[idx];
    __syncthreads();

    int t = blockIdx.x * blockDim.x + threadIdx.x;
    int quad = t >> 1;          // group of 4 nodes
    int part = t & 1;           // output half: [part*32, part*32+32)
    int n0 = quad * 4;
    if (n0 >= N_NODES) return;  // N_NODES % 4 == 0

    unsigned long long acc[4][16];
#pragma unroll
    for (int p = 0; p < 16; p++) {
        unsigned long long b2 = pack_f32(sB[part * 32 + p * 2], sB[part * 32 + p * 2 + 1]);
#pragma unroll
        for (int n = 0; n < 4; n++) acc[n][p] = b2;
    }

    const float4* aB = (const float4*)(agg + (long)n0 * DIN);
    const float4* hB = (const float4*)(hin + (long)n0 * DIN);
    constexpr int R4 = DIN / 4;  // float4 per row

    for (int k4 = 0; k4 < DIN / 4; k4++) {
        float4 av[4], hv[4];
#pragma unroll
        for (int n = 0; n < 4; n++) {
            av[n] = aB[(long)n * R4 + k4];
            hv[n] = hB[(long)n * R4 + k4];
        }
#pragma unroll
        for (int kk = 0; kk < 4; kk++) {
            int k = k4 * 4 + kk;
            const unsigned long long* wr =
                (const unsigned long long*)(sWrel + k * 64 + part * 32);
            const unsigned long long* wo =
                (const unsigned long long*)(sWroot + k * 64 + part * 32);
            unsigned long long ad[4], hd[4];
#pragma unroll
            for (int n = 0; n < 4; n++) {
                float as = (kk == 0) ? av[n].x : (kk == 1) ? av[n].y : (kk == 2) ? av[n].z : av[n].w;
                float hs = (kk == 0) ? hv[n].x : (kk == 1) ? hv[n].y : (kk == 2) ? hv[n].z : hv[n].w;
                ad[n] = dup_f32(as);
                hd[n] = dup_f32(hs);
            }
#pragma unroll
            for (int p = 0; p < 16; p++) {
                unsigned long long w1 = wr[p];
                unsigned long long w2 = wo[p];
#pragma unroll
                for (int n = 0; n < 4; n++) {
                    fma2(acc[n][p], w1, ad[n]);
                    fma2(acc[n][p], w2, hd[n]);
                }
            }
        }
    }

#pragma unroll
    for (int n = 0; n < 4; n++) {
        float4* d = (float4*)(hout + (long)(n0 + n) * 64 + part * 32);
#pragma unroll
        for (int j = 0; j < 8; j += 2) {
            float2 f0 = unpack_f32(acc[n][j]);
            float2 f1 = unpack_f32(acc[n][j + 1]);
            d[j / 2] = make_float4(fmaxf(f0.x, 0.f), fmaxf(f0.y, 0.f),
                                   fmaxf(f1.x, 0.f), fmaxf(f1.y, 0.f));
        }
        float4* d2 = d + 4;
#pragma unroll
        for (int j = 8; j < 16; j += 2) {
            float2 f0 = unpack_f32(acc[n][j]);
            float2 f1 = unpack_f32(acc[n][j + 1]);
            d2[(j - 8) / 2] = make_float4(fmaxf(f0.x, 0.f), fmaxf(f0.y, 0.f),
                                          fmaxf(f1.x, 0.f), fmaxf(f1.y, 0.f));
        }
    }
}

// ---------------- K6: global mean pool (sum + count) -----------------------
__global__ void pool_kernel(const int* __restrict__ batch) {
    int t = blockIdx.x * blockDim.x + threadIdx.x;
    int i = t >> 4;
    int j = t & 15;
    if (i >= N_NODES) return;
    int g = batch[i];
    float4 v = ((const float4*)g_h2)[(long)i * 16 + j];
    float* p = g_gsum + ((long)g * 16 + j) * 4;
    asm volatile("red.global.add.v4.f32 [%0], {%1,%2,%3,%4};"
                 :: "l"(p), "f"(v.x), "f"(v.y), "f"(v.z), "f"(v.w) : "memory");
    if (j == 0) atomicAdd(&g_gcnt[g], 1.0f);
}

// ---------------- K7: classifier -------------------------------------------
__global__ void cls_kernel(const float* __restrict__ W_cls,
                           const float* __restrict__ b_cls,
                           float* __restrict__ out) {
    __shared__ float sp[64];
    int g = blockIdx.x;
    float c = fmaxf(g_gcnt[g], 1.0f);
    sp[threadIdx.x] = g_gsum[(long)g * 64 + threadIdx.x] / c;
    __syncthreads();
    if (threadIdx.x < 10) {
        int o = threadIdx.x;
        float acc = b_cls[o];
#pragma unroll
        for (int k = 0; k < 64; k++) acc += sp[k] * W_cls[o * 64 + k];
        out[(long)g * 10 + o] = acc;
    }
}

// ---------------- launch ----------------------------------------------------
extern "C" void kernel_launch(void* const* d_in, const int* in_sizes, int n_in,
                              void* d_out, int out_size) {
    const int* x     = (const int*)d_in[0];
    const int* edge  = (const int*)d_in[1];
    const int* batch = (const int*)d_in[2];

    // locate shape_emb (the unique size-128 tensor among params)
    int se = -1;
    for (int i = 3; i < n_in; i++) {
        if (in_sizes[i] == 128) { se = i; break; }
    }
    if (se < 0) se = (n_in == 16) ? 4 : 3;

    const float* shape_emb = (const float*)d_in[se + 0];
    const float* color_emb = (const float*)d_in[se + 1];
    const float* W_pre     = (const float*)d_in[se + 2];
    const float* b_pre     = (const float*)d_in[se + 3];
    const float* W_rel1    = (const float*)d_in[se + 4];
    const float* b_rel1    = (const float*)d_in[se + 5];
    const float* W_root1   = (const float*)d_in[se + 6];
    const float* W_rel2    = (const float*)d_in[se + 7];
    const float* b_rel2    = (const float*)d_in[se + 8];
    const float* W_root2   = (const float*)d_in[se + 9];
    const float* W_cls     = (const float*)d_in[se + 10];
    const float* b_cls     = (const float*)d_in[se + 11];

    float* out = (float*)d_out;

    void *p_agg1, *p_agg2, *p_gsum, *p_gcnt, *p_h0, *p_h1, *p_h2, *p_deg, *p_cur;
    cudaGetSymbolAddress(&p_agg1, g_agg1);
    cudaGetSymbolAddress(&p_agg2, g_agg2);
    cudaGetSymbolAddress(&p_gsum, g_gsum);
    cudaGetSymbolAddress(&p_gcnt, g_gcnt);
    cudaGetSymbolAddress(&p_h0, g_h0);
    cudaGetSymbolAddress(&p_h1, g_h1);
    cudaGetSymbolAddress(&p_h2, g_h2);
    cudaGetSymbolAddress(&p_deg, g_deg);
    cudaGetSymbolAddress(&p_cur, g_cur);

    cudaMemsetAsync(p_deg, 0, (size_t)N_NODES * sizeof(int));
    cudaMemsetAsync(p_cur, 0, (size_t)N_NODES * sizeof(int));
    cudaMemsetAsync(p_gsum, 0, (size_t)N_GRAPHS * 64 * sizeof(float));
    cudaMemsetAsync(p_gcnt, 0, (size_t)N_GRAPHS * sizeof(float));

    const int* src = edge;
    const int* dstp = edge + N_EDGES;

    // CSR build (reused by both layers)
    hist_kernel<<<(N_EDGES + 255) / 256, 256>>>(dstp);
    scan_kernel<<<1, 1024>>>();
    scatter_kernel<<<(N_EDGES + 255) / 256, 256>>>(src, dstp);

    // K1: embed + pre
    embed_pre_kernel<<<(N_NODES + 255) / 256, 256>>>(x, shape_emb, color_emb, W_pre, b_pre);

    // layer 1 aggregation (D=32, 2 parts/node)
    {
        int threads = N_NODES * 2;
        csr_agg_kernel<32, 1><<<(threads + 255) / 256, 256>>>(
            (const float*)p_h0, (float*)p_agg1);
    }
    // layer 1 node update
    {
        int threads = (N_NODES / 4) * 2;
        node_update_kernel<32><<<(threads + 127) / 128, 128>>>(
            (const float*)p_agg1, (const float*)p_h0, W_rel1, b_rel1, W_root1, (float*)p_h1);
    }
    // layer 2 aggregation (D=64, 4 parts/node)
    {
        int threads = N_NODES * 4;
        csr_agg_kernel<64, 2><<<(threads + 255) / 256, 256>>>(
            (const float*)p_h1, (float*)p_agg2);
    }
    // layer 2 node update
    {
        int threads = (N_NODES / 4) * 2;
        node_update_kernel<64><<<(threads + 127) / 128, 128>>>(
            (const float*)p_agg2, (const float*)p_h1, W_rel2, b_rel2, W_root2, (float*)p_h2);
    }

    // pooling
    {
        int threads = N_NODES * 16;
        pool_kernel<<<(threads + 255) / 256, 256>>>(batch);
    }

    // classifier
    cls_kernel<<<N_GRAPHS, 64>>>(W_cls, b_cls, out);

    (void)out_size;
}

// round 3
// speedup vs baseline: 1.4130x; 1.3571x over previous
#include <cuda_runtime.h>
#include <cuda_bf16.h>

#define N_NODES 100000
#define N_EDGES 1200000
#define N_GRAPHS 1000

#define SCAN_CHUNK 128
#define N_CHUNKS ((N_NODES + SCAN_CHUNK - 1) / SCAN_CHUNK)  // 782

// ---------------- scratch (device globals; no allocation allowed) ----------
__device__ float g_h0[N_NODES * 32];    // after embed+pre MLP
__device__ float g_agg1[N_NODES * 32];  // edge agg layer 1
__device__ float g_h1[N_NODES * 64];    // after layer 1
__device__ float g_agg2[N_NODES * 64];  // edge agg layer 2
__device__ float g_h2[N_NODES * 64];    // after layer 2

// CSR scratch
__device__ int g_deg[N_NODES];
__device__ int g_off[N_NODES + 1];
__device__ int g_cur[N_NODES];
__device__ int g_srcs[N_EDGES];
__device__ int g_chunksum[N_CHUNKS];
__device__ int g_chunkbase[N_CHUNKS];

// graph pooling offsets
__device__ int g_gdeg[N_GRAPHS];
__device__ int g_goff[N_GRAPHS + 1];

// ---------------- packed f32x2 helpers (sm_103a) ----------------------------
__device__ __forceinline__ unsigned long long dup_f32(float a) {
    unsigned long long r;
    asm("mov.b64 %0, {%1, %1};" : "=l"(r) : "f"(a));
    return r;
}
__device__ __forceinline__ unsigned long long pack_f32(float lo, float hi) {
    unsigned long long r;
    asm("mov.b64 %0, {%1, %2};" : "=l"(r) : "f"(lo), "f"(hi));
    return r;
}
__device__ __forceinline__ void fma2(unsigned long long& d,
                                     unsigned long long a,
                                     unsigned long long b) {
    asm("fma.rn.f32x2 %0, %1, %2, %0;" : "+l"(d) : "l"(a), "l"(b));
}
__device__ __forceinline__ float2 unpack_f32(unsigned long long v) {
    float lo, hi;
    asm("mov.b64 {%0, %1}, %2;" : "=f"(lo), "=f"(hi) : "l"(v));
    return make_float2(lo, hi);
}

// ---------------- CSR build --------------------------------------------------
__global__ void hist_kernel(const int* __restrict__ dst) {
    int e = blockIdx.x * blockDim.x + threadIdx.x;
    if (e >= N_EDGES) return;
    atomicAdd(&g_deg[dst[e]], 1);
}

// Phase A: warp per 128-element chunk -> chunk sums
__global__ void scanA_kernel() {
    int t = blockIdx.x * blockDim.x + threadIdx.x;
    int warpId = t >> 5;
    int lane = t & 31;
    if (warpId >= N_CHUNKS) return;
    int idx = warpId * SCAN_CHUNK + lane * 4;
    int4 v = make_int4(0, 0, 0, 0);
    if (idx < N_NODES) v = *(const int4*)(g_deg + idx);  // N_NODES % 4 == 0
    int s = v.x + v.y + v.z + v.w;
#pragma unroll
    for (int off = 16; off > 0; off >>= 1)
        s += __shfl_xor_sync(0xffffffffu, s, off);
    if (lane == 0) g_chunksum[warpId] = s;
}

// Phase B: one block scans the chunk sums (N_CHUNKS=782 < 1024)
__global__ void scanB_kernel() {
    __shared__ int sv[1024];
    int t = threadIdx.x;
    int v = (t < N_CHUNKS) ? g_chunksum[t] : 0;
    sv[t] = v;
    __syncthreads();
#pragma unroll
    for (int off = 1; off < 1024; off <<= 1) {
        int u = (t >= off) ? sv[t - off] : 0;
        __syncthreads();
        sv[t] += u;
        __syncthreads();
    }
    if (t < N_CHUNKS) g_chunkbase[t] = sv[t] - v;  // exclusive
}

// Phase C: warp per chunk writes per-element exclusive offsets
__global__ void scanC_kernel() {
    int t = blockIdx.x * blockDim.x + threadIdx.x;
    int warpId = t >> 5;
    int lane = t & 31;
    if (warpId >= N_CHUNKS) return;
    int idx = warpId * SCAN_CHUNK + lane * 4;
    int4 v = make_int4(0, 0, 0, 0);
    if (idx < N_NODES) v = *(const int4*)(g_deg + idx);
    int s = v.x + v.y + v.z + v.w;
    // inclusive warp scan of s
    int incl = s;
#pragma unroll
    for (int off = 1; off < 32; off <<= 1) {
        int u = __shfl_up_sync(0xffffffffu, incl, off);
        if (lane >= off) incl += u;
    }
    int base = g_chunkbase[warpId] + (incl - s);
    if (idx < N_NODES) {
        int4 o;
        o.x = base;
        o.y = base + v.x;
        o.z = o.y + v.y;
        o.w = o.z + v.z;
        *(int4*)(g_off + idx) = o;
        if (idx + 4 == N_NODES) g_off[N_NODES] = o.w + v.w;
    }
}

__global__ void scatter_kernel(const int* __restrict__ src,
                               const int* __restrict__ dst) {
    int e = blockIdx.x * blockDim.x + threadIdx.x;
    if (e >= N_EDGES) return;
    int d = dst[e];
    int p = atomicAdd(&g_cur[d], 1);
    g_srcs[g_off[d] + p] = src[e];
}

// ---------------- graph offsets (batch is sorted) ---------------------------
__global__ void ghist_kernel(const int* __restrict__ batch) {
    int i = blockIdx.x * blockDim.x + threadIdx.x;
    if (i >= N_NODES) return;
    atomicAdd(&g_gdeg[batch[i]], 1);
}

__global__ void gscan_kernel() {
    __shared__ int sv[1024];
    int t = threadIdx.x;
    int v = (t < N_GRAPHS) ? g_gdeg[t] : 0;
    sv[t] = v;
    __syncthreads();
#pragma unroll
    for (int off = 1; off < 1024; off <<= 1) {
        int u = (t >= off) ? sv[t - off] : 0;
        __syncthreads();
        sv[t] += u;
        __syncthreads();
    }
    if (t < N_GRAPHS) {
        g_goff[t] = sv[t] - v;
        if (t == N_GRAPHS - 1) g_goff[N_GRAPHS] = sv[t];
    }
}

// ---------------- K1: embed + pre-linear + relu ----------------------------
__global__ void embed_pre_kernel(const int* __restrict__ x,
                                 const float* __restrict__ shape_emb,
                                 const float* __restrict__ color_emb,
                                 const float* __restrict__ W_pre,
                                 const float* __restrict__ b_pre) {
    __shared__ float sSE[16 * 8];
    __shared__ float sCE[8 * 8];
    __shared__ float sW[32 * 16];
    __shared__ float sB[32];
    for (int idx = threadIdx.x; idx < 128; idx += blockDim.x) sSE[idx] = shape_emb[idx];
    for (int idx = threadIdx.x; idx < 64; idx += blockDim.x)  sCE[idx] = color_emb[idx];
    for (int idx = threadIdx.x; idx < 512; idx += blockDim.x) sW[idx]  = W_pre[idx];
    if (threadIdx.x < 32) sB[threadIdx.x] = b_pre[threadIdx.x];
    __syncthreads();

    int i = blockIdx.x * blockDim.x + threadIdx.x;
    if (i >= N_NODES) return;
    int2 xi = ((const int2*)x)[i];
    float in[16];
#pragma unroll
    for (int k = 0; k < 8; k++) {
        in[k]     = sSE[xi.x * 8 + k];
        in[8 + k] = sCE[xi.y * 8 + k];
    }
    float out[32];
#pragma unroll
    for (int o = 0; o < 32; o++) {
        float acc = sB[o];
#pragma unroll
        for (int k = 0; k < 16; k++) acc += sW[o * 16 + k] * in[k];
        out[o] = fmaxf(acc, 0.0f);
    }
    float4* dst = (float4*)(g_h0 + (long)i * 32);
#pragma unroll
    for (int j = 0; j < 8; j++)
        dst[j] = make_float4(out[j * 4], out[j * 4 + 1], out[j * 4 + 2], out[j * 4 + 3]);
}

// ---------------- CSR aggregation (no atomics) ------------------------------
template <int D, int LOGP>
__global__ void csr_agg_kernel(const float* __restrict__ hin,
                               float* __restrict__ agg) {
    constexpr int PARTS = D / 16;
    int t = blockIdx.x * blockDim.x + threadIdx.x;
    int node = t >> LOGP;
    int part = t & (PARTS - 1);
    if (node >= N_NODES) return;
    int lo = g_off[node];
    int hi = g_off[node + 1];

    float4 a0 = make_float4(0.f, 0.f, 0.f, 0.f);
    float4 a1 = a0, a2 = a0, a3 = a0;

    const float4* base = (const float4*)hin + part * 4;
    for (int e = lo; e < hi; e++) {
        int s = g_srcs[e];
        const float4* row = base + (long)s * (D / 4);
        float4 v0 = row[0], v1 = row[1], v2 = row[2], v3 = row[3];
        a0.x += v0.x; a0.y += v0.y; a0.z += v0.z; a0.w += v0.w;
        a1.x += v1.x; a1.y += v1.y; a1.z += v1.z; a1.w += v1.w;
        a2.x += v2.x; a2.y += v2.y; a2.z += v2.z; a2.w += v2.w;
        a3.x += v3.x; a3.y += v3.y; a3.z += v3.z; a3.w += v3.w;
    }
    float4* out = (float4*)agg + (long)node * (D / 4) + part * 4;
    out[0] = a0; out[1] = a1; out[2] = a2; out[3] = a3;
}

// ---------------- node update: agg@Wrel^T + b + h@Wroot^T, relu ------------
template <int DIN>
__global__ void __launch_bounds__(128)
node_update_kernel(const float* __restrict__ agg,
                   const float* __restrict__ hin,
                   const float* __restrict__ Wrel,
                   const float* __restrict__ brel,
                   const float* __restrict__ Wroot,
                   float* __restrict__ hout) {
    __shared__ float sWrel[DIN * 64];   // [k][o]
    __shared__ float sWroot[DIN * 64];  // [k][o]
    __shared__ float sB[64];
    for (int idx = threadIdx.x; idx < DIN * 64; idx += blockDim.x) {
        int o = idx & 63, k = idx >> 6;
        sWrel[idx]  = Wrel[o * DIN + k];
        sWroot[idx] = Wroot[o * DIN + k];
    }
    for (int idx = threadIdx.x; idx < 64; idx += blockDim.x) sB[idx] = brel[idx];
    __syncthreads();

    int t = blockIdx.x * blockDim.x + threadIdx.x;
    int quad = t >> 1;          // group of 4 nodes
    int part = t & 1;           // output half: [part*32, part*32+32)
    int n0 = quad * 4;
    if (n0 >= N_NODES) return;  // N_NODES % 4 == 0

    unsigned long long acc[4][16];
#pragma unroll
    for (int p = 0; p < 16; p++) {
        unsigned long long b2 = pack_f32(sB[part * 32 + p * 2], sB[part * 32 + p * 2 + 1]);
#pragma unroll
        for (int n = 0; n < 4; n++) acc[n][p] = b2;
    }

    const float4* aB = (const float4*)(agg + (long)n0 * DIN);
    const float4* hB = (const float4*)(hin + (long)n0 * DIN);
    constexpr int R4 = DIN / 4;

    for (int k4 = 0; k4 < DIN / 4; k4++) {
        float4 av[4], hv[4];
#pragma unroll
        for (int n = 0; n < 4; n++) {
            av[n] = aB[(long)n * R4 + k4];
            hv[n] = hB[(long)n * R4 + k4];
        }
#pragma unroll
        for (int kk = 0; kk < 4; kk++) {
            int k = k4 * 4 + kk;
            const unsigned long long* wr =
                (const unsigned long long*)(sWrel + k * 64 + part * 32);
            const unsigned long long* wo =
                (const unsigned long long*)(sWroot + k * 64 + part * 32);
            unsigned long long ad[4], hd[4];
#pragma unroll
            for (int n = 0; n < 4; n++) {
                float as = (kk == 0) ? av[n].x : (kk == 1) ? av[n].y : (kk == 2) ? av[n].z : av[n].w;
                float hs = (kk == 0) ? hv[n].x : (kk == 1) ? hv[n].y : (kk == 2) ? hv[n].z : hv[n].w;
                ad[n] = dup_f32(as);
                hd[n] = dup_f32(hs);
            }
#pragma unroll
            for (int p = 0; p < 16; p++) {
                unsigned long long w1 = wr[p];
                unsigned long long w2 = wo[p];
#pragma unroll
                for (int n = 0; n < 4; n++) {
                    fma2(acc[n][p], w1, ad[n]);
                    fma2(acc[n][p], w2, hd[n]);
                }
            }
        }
    }

#pragma unroll
    for (int n = 0; n < 4; n++) {
        float4* d = (float4*)(hout + (long)(n0 + n) * 64 + part * 32);
#pragma unroll
        for (int j = 0; j < 16; j += 2) {
            float2 f0 = unpack_f32(acc[n][j]);
            float2 f1 = unpack_f32(acc[n][j + 1]);
            d[j / 2] = make_float4(fmaxf(f0.x, 0.f), fmaxf(f0.y, 0.f),
                                   fmaxf(f1.x, 0.f), fmaxf(f1.y, 0.f));
        }
    }
}

// ---------------- fused mean-pool + classifier (one block per graph) -------
__global__ void __launch_bounds__(64)
pool_cls_kernel(const float* __restrict__ W_cls,
                const float* __restrict__ b_cls,
                float* __restrict__ out) {
    __shared__ float sp[64];
    int g = blockIdx.x;
    int lo = g_goff[g];
    int hi = g_goff[g + 1];
    int tid = threadIdx.x;

    float acc = 0.0f;
    int i = lo;
    for (; i + 4 <= hi; i += 4) {
        acc += g_h2[(long)(i + 0) * 64 + tid];
        acc += g_h2[(long)(i + 1) * 64 + tid];
        acc += g_h2[(long)(i + 2) * 64 + tid];
        acc += g_h2[(long)(i + 3) * 64 + tid];
    }
    for (; i < hi; i++) acc += g_h2[(long)i * 64 + tid];

    float cnt = fmaxf((float)(hi - lo), 1.0f);
    sp[tid] = acc / cnt;
    __syncthreads();

    if (tid < 10) {
        float r = b_cls[tid];
#pragma unroll
        for (int k = 0; k < 64; k++) r += sp[k] * W_cls[tid * 64 + k];
        out[(long)g * 10 + tid] = r;
    }
}

// ---------------- launch ----------------------------------------------------
extern "C" void kernel_launch(void* const* d_in, const int* in_sizes, int n_in,
                              void* d_out, int out_size) {
    const int* x     = (const int*)d_in[0];
    const int* edge  = (const int*)d_in[1];
    const int* batch = (const int*)d_in[2];

    int se = -1;
    for (int i = 3; i < n_in; i++) {
        if (in_sizes[i] == 128) { se = i; break; }
    }
    if (se < 0) se = (n_in == 16) ? 4 : 3;

    const float* shape_emb = (const float*)d_in[se + 0];
    const float* color_emb = (const float*)d_in[se + 1];
    const float* W_pre     = (const float*)d_in[se + 2];
    const float* b_pre     = (const float*)d_in[se + 3];
    const float* W_rel1    = (const float*)d_in[se + 4];
    const float* b_rel1    = (const float*)d_in[se + 5];
    const float* W_root1   = (const float*)d_in[se + 6];
    const float* W_rel2    = (const float*)d_in[se + 7];
    const float* b_rel2    = (const float*)d_in[se + 8];
    const float* W_root2   = (const float*)d_in[se + 9];
    const float* W_cls     = (const float*)d_in[se + 10];
    const float* b_cls     = (const float*)d_in[se + 11];

    float* out = (float*)d_out;

    void *p_agg1, *p_agg2, *p_h0, *p_h1, *p_h2, *p_deg, *p_cur, *p_gdeg;
    cudaGetSymbolAddress(&p_agg1, g_agg1);
    cudaGetSymbolAddress(&p_agg2, g_agg2);
    cudaGetSymbolAddress(&p_h0, g_h0);
    cudaGetSymbolAddress(&p_h1, g_h1);
    cudaGetSymbolAddress(&p_h2, g_h2);
    cudaGetSymbolAddress(&p_deg, g_deg);
    cudaGetSymbolAddress(&p_cur, g_cur);
    cudaGetSymbolAddress(&p_gdeg, g_gdeg);

    cudaMemsetAsync(p_deg, 0, (size_t)N_NODES * sizeof(int));
    cudaMemsetAsync(p_cur, 0, (size_t)N_NODES * sizeof(int));
    cudaMemsetAsync(p_gdeg, 0, (size_t)N_GRAPHS * sizeof(int));

    const int* src = edge;
    const int* dstp = edge + N_EDGES;

    // CSR build (parallel scan)
    hist_kernel<<<(N_EDGES + 255) / 256, 256>>>(dstp);
    scanA_kernel<<<(N_CHUNKS * 32 + 255) / 256, 256>>>();
    scanB_kernel<<<1, 1024>>>();
    scanC_kernel<<<(N_CHUNKS * 32 + 255) / 256, 256>>>();
    scatter_kernel<<<(N_EDGES + 255) / 256, 256>>>(src, dstp);

    // graph offsets for pooling (batch sorted)
    ghist_kernel<<<(N_NODES + 255) / 256, 256>>>(batch);
    gscan_kernel<<<1, 1024>>>();

    // embed + pre
    embed_pre_kernel<<<(N_NODES + 255) / 256, 256>>>(x, shape_emb, color_emb, W_pre, b_pre);

    // layer 1
    {
        int threads = N_NODES * 2;
        csr_agg_kernel<32, 1><<<(threads + 255) / 256, 256>>>(
            (const float*)p_h0, (float*)p_agg1);
    }
    {
        int threads = (N_NODES / 4) * 2;
        node_update_kernel<32><<<(threads + 127) / 128, 128>>>(
            (const float*)p_agg1, (const float*)p_h0, W_rel1, b_rel1, W_root1, (float*)p_h1);
    }
    // layer 2
    {
        int threads = N_NODES * 4;
        csr_agg_kernel<64, 2><<<(threads + 255) / 256, 256>>>(
            (const float*)p_h1, (float*)p_agg2);
    }
    {
        int threads = (N_NODES / 4) * 2;
        node_update_kernel<64><<<(threads + 127) / 128, 128>>>(
            (const float*)p_agg2, (const float*)p_h1, W_rel2, b_rel2, W_root2, (float*)p_h2);
    }

    // fused pool + classifier
    pool_cls_kernel<<<N_GRAPHS, 64>>>(W_cls, b_cls, out);

    (void)out_size;
}

// round 5
// speedup vs baseline: 1.5430x; 1.0920x over previous
#include <cuda_runtime.h>
#include <cuda_bf16.h>

#define N_NODES 100000
#define N_EDGES 1200000
#define N_GRAPHS 1000

#define SCAN_CHUNK 128
#define N_CHUNKS ((N_NODES + SCAN_CHUNK - 1) / SCAN_CHUNK)  // 782

#define EMB_BLOCKS ((N_NODES + 255) / 256)   // 391
#define SCAT_BLOCKS ((N_EDGES + 255) / 256)  // 4688

// ---------------- scratch (device globals; no allocation allowed) ----------
__device__ float g_h0[N_NODES * 32];
__device__ float g_agg1[N_NODES * 32];
__device__ float g_h1[N_NODES * 64];
__device__ float g_agg2[N_NODES * 64];
__device__ float g_h2[N_NODES * 64];

// zeroed-per-call block: [deg | cur | gdeg]  (single memset)
__device__ int g_zero[N_NODES * 2 + N_GRAPHS];
#define G_DEG  (g_zero)
#define G_CUR  (g_zero + N_NODES)
#define G_GDEG (g_zero + 2 * N_NODES)

__device__ int g_off[N_NODES + 1];
__device__ int g_srcs[N_EDGES];
__device__ int g_chunksum[N_CHUNKS];
__device__ int g_chunkbase[N_CHUNKS];
__device__ int g_goff[N_GRAPHS + 1];

// ---------------- packed f32x2 helpers (sm_103a) ----------------------------
__device__ __forceinline__ unsigned long long dup_f32(float a) {
    unsigned long long r;
    asm("mov.b64 %0, {%1, %1};" : "=l"(r) : "f"(a));
    return r;
}
__device__ __forceinline__ unsigned long long pack_f32(float lo, float hi) {
    unsigned long long r;
    asm("mov.b64 %0, {%1, %2};" : "=l"(r) : "f"(lo), "f"(hi));
    return r;
}
__device__ __forceinline__ void fma2(unsigned long long& d,
                                     unsigned long long a,
                                     unsigned long long b) {
    asm("fma.rn.f32x2 %0, %1, %2, %0;" : "+l"(d) : "l"(a), "l"(b));
}
__device__ __forceinline__ float2 unpack_f32(unsigned long long v) {
    float lo, hi;
    asm("mov.b64 {%0, %1}, %2;" : "=f"(lo), "=f"(hi) : "l"(v));
    return make_float2(lo, hi);
}

// ---------------- K1: edge histogram + graph histogram (fused) --------------
__global__ void hist_all_kernel(const int* __restrict__ dst,
                                const int* __restrict__ batch) {
    int t = blockIdx.x * blockDim.x + threadIdx.x;
    if (t < N_EDGES) atomicAdd(&G_DEG[dst[t]], 1);
    if (t < N_NODES) atomicAdd(&G_GDEG[batch[t]], 1);
}

// ---------------- K2: chunk sums ---------------------------------------------
__global__ void scanA_kernel() {
    int t = blockIdx.x * blockDim.x + threadIdx.x;
    int warpId = t >> 5;
    int lane = t & 31;
    if (warpId >= N_CHUNKS) return;
    int idx = warpId * SCAN_CHUNK + lane * 4;
    int4 v = make_int4(0, 0, 0, 0);
    if (idx < N_NODES) v = *(const int4*)(G_DEG + idx);
    int s = v.x + v.y + v.z + v.w;
#pragma unroll
    for (int off = 16; off > 0; off >>= 1)
        s += __shfl_xor_sync(0xffffffffu, s, off);
    if (lane == 0) g_chunksum[warpId] = s;
}

// ---------------- K3: two independent one-block scans (2 blocks) ------------
__global__ void scan2_kernel() {
    __shared__ int sv[1024];
    int t = threadIdx.x;
    if (blockIdx.x == 0) {
        int v = (t < N_CHUNKS) ? g_chunksum[t] : 0;
        sv[t] = v;
        __syncthreads();
#pragma unroll
        for (int off = 1; off < 1024; off <<= 1) {
            int u = (t >= off) ? sv[t - off] : 0;
            __syncthreads();
            sv[t] += u;
            __syncthreads();
        }
        if (t < N_CHUNKS) g_chunkbase[t] = sv[t] - v;
    } else {
        int v = (t < N_GRAPHS) ? G_GDEG[t] : 0;
        sv[t] = v;
        __syncthreads();
#pragma unroll
        for (int off = 1; off < 1024; off <<= 1) {
            int u = (t >= off) ? sv[t - off] : 0;
            __syncthreads();
            sv[t] += u;
            __syncthreads();
        }
        if (t < N_GRAPHS) {
            g_goff[t] = sv[t] - v;
            if (t == N_GRAPHS - 1) g_goff[N_GRAPHS] = sv[t];
        }
    }
}

// ---------------- K4: per-node exclusive offsets -----------------------------
__global__ void scanC_kernel() {
    int t = blockIdx.x * blockDim.x + threadIdx.x;
    int warpId = t >> 5;
    int lane = t & 31;
    if (warpId >= N_CHUNKS) return;
    int idx = warpId * SCAN_CHUNK + lane * 4;
    int4 v = make_int4(0, 0, 0, 0);
    if (idx < N_NODES) v = *(const int4*)(G_DEG + idx);
    int s = v.x + v.y + v.z + v.w;
    int incl = s;
#pragma unroll
    for (int off = 1; off < 32; off <<= 1) {
        int u = __shfl_up_sync(0xffffffffu, incl, off);
        if (lane >= off) incl += u;
    }
    int base = g_chunkbase[warpId] + (incl - s);
    if (idx < N_NODES) {
        int4 o;
        o.x = base;
        o.y = base + v.x;
        o.z = o.y + v.y;
        o.w = o.z + v.z;
        *(int4*)(g_off + idx) = o;
        if (idx + 4 == N_NODES) g_off[N_NODES] = o.w + v.w;
    }
}

// ---------------- K5: fused scatter (CSR fill) + embed+pre MLP --------------
__global__ void __launch_bounds__(256)
scatter_embed_kernel(const int* __restrict__ src,
                     const int* __restrict__ dst,
                     const int* __restrict__ x,
                     const float* __restrict__ shape_emb,
                     const float* __restrict__ color_emb,
                     const float* __restrict__ W_pre,
                     const float* __restrict__ b_pre) {
    __shared__ float sTab[128 + 64 + 512 + 32];
    if (blockIdx.x < EMB_BLOCKS) {
        float* sSE = sTab;
        float* sCE = sTab + 128;
        float* sW  = sTab + 192;
        float* sB  = sTab + 704;
        for (int idx = threadIdx.x; idx < 128; idx += 256) sSE[idx] = shape_emb[idx];
        for (int idx = threadIdx.x; idx < 64; idx += 256)  sCE[idx] = color_emb[idx];
        for (int idx = threadIdx.x; idx < 512; idx += 256) sW[idx]  = W_pre[idx];
        if (threadIdx.x < 32) sB[threadIdx.x] = b_pre[threadIdx.x];
        __syncthreads();

        int i = blockIdx.x * 256 + threadIdx.x;
        if (i >= N_NODES) return;
        int2 xi = ((const int2*)x)[i];
        float in[16];
#pragma unroll
        for (int k = 0; k < 8; k++) {
            in[k]     = sSE[xi.x * 8 + k];
            in[8 + k] = sCE[xi.y * 8 + k];
        }
        float out[32];
#pragma unroll
        for (int o = 0; o < 32; o++) {
            float acc = sB[o];
#pragma unroll
            for (int k = 0; k < 16; k++) acc += sW[o * 16 + k] * in[k];
            out[o] = fmaxf(acc, 0.0f);
        }
        float4* dstp = (float4*)(g_h0 + (long)i * 32);
#pragma unroll
        for (int j = 0; j < 8; j++)
            dstp[j] = make_float4(out[j * 4], out[j * 4 + 1], out[j * 4 + 2], out[j * 4 + 3]);
    } else {
        int e = (blockIdx.x - EMB_BLOCKS) * 256 + threadIdx.x;
        if (e >= N_EDGES) return;
        int d = dst[e];
        int p = atomicAdd(&G_CUR[d], 1);
        g_srcs[g_off[d] + p] = src[e];
    }
}

// ---------------- CSR aggregation (no atomics, 2-edge unroll) ----------------
template <int D, int LOGP>
__global__ void csr_agg_kernel(const float* __restrict__ hin,
                               float* __restrict__ agg) {
    constexpr int PARTS = D / 16;
    int t = blockIdx.x * blockDim.x + threadIdx.x;
    int node = t >> LOGP;
    int part = t & (PARTS - 1);
    if (node >= N_NODES) return;
    int lo = g_off[node];
    int hi = g_off[node + 1];

    float4 a0 = make_float4(0.f, 0.f, 0.f, 0.f);
    float4 a1 = a0, a2 = a0, a3 = a0;

    const float4* base = (const float4*)hin + part * 4;
    int e = lo;
    for (; e + 2 <= hi; e += 2) {
        int s0 = g_srcs[e];
        int s1 = g_srcs[e + 1];
        const float4* r0 = base + (long)s0 * (D / 4);
        const float4* r1 = base + (long)s1 * (D / 4);
        float4 u0 = r0[0], u1 = r0[1], u2 = r0[2], u3 = r0[3];
        float4 w0 = r1[0], w1 = r1[1], w2 = r1[2], w3 = r1[3];
        a0.x += u0.x; a0.y += u0.y; a0.z += u0.z; a0.w += u0.w;
        a1.x += u1.x; a1.y += u1.y; a1.z += u1.z; a1.w += u1.w;
        a2.x += u2.x; a2.y += u2.y; a2.z += u2.z; a2.w += u2.w;
        a3.x += u3.x; a3.y += u3.y; a3.z += u3.z; a3.w += u3.w;
        a0.x += w0.x; a0.y += w0.y; a0.z += w0.z; a0.w += w0.w;
        a1.x += w1.x; a1.y += w1.y; a1.z += w1.z; a1.w += w1.w;
        a2.x += w2.x; a2.y += w2.y; a2.z += w2.z; a2.w += w2.w;
        a3.x += w3.x; a3.y += w3.y; a3.z += w3.z; a3.w += w3.w;
    }
    if (e < hi) {
        int s = g_srcs[e];
        const float4* row = base + (long)s * (D / 4);
        float4 v0 = row[0], v1 = row[1], v2 = row[2], v3 = row[3];
        a0.x += v0.x; a0.y += v0.y; a0.z += v0.z; a0.w += v0.w;
        a1.x += v1.x; a1.y += v1.y; a1.z += v1.z; a1.w += v1.w;
        a2.x += v2.x; a2.y += v2.y; a2.z += v2.z; a2.w += v2.w;
        a3.x += v3.x; a3.y += v3.y; a3.z += v3.z; a3.w += v3.w;
    }
    float4* out = (float4*)agg + (long)node * (D / 4) + part * 4;
    out[0] = a0; out[1] = a1; out[2] = a2; out[3] = a3;
}

// ---------------- node update: agg@Wrel^T + b + h@Wroot^T, relu ------------
template <int DIN>
__global__ void __launch_bounds__(128)
node_update_kernel(const float* __restrict__ agg,
                   const float* __restrict__ hin,
                   const float* __restrict__ Wrel,
                   const float* __restrict__ brel,
                   const float* __restrict__ Wroot,
                   float* __restrict__ hout) {
    __shared__ float sWrel[DIN * 64];
    __shared__ float sWroot[DIN * 64];
    __shared__ float sB[64];
    for (int idx = threadIdx.x; idx < DIN * 64; idx += blockDim.x) {
        int o = idx & 63, k = idx >> 6;
        sWrel[idx]  = Wrel[o * DIN + k];
        sWroot[idx] = Wroot[o * DIN + k];
    }
    for (int idx = threadIdx.x; idx < 64; idx += blockDim.x) sB[idx] = brel[idx];
    __syncthreads();

    int t = blockIdx.x * blockDim.x + threadIdx.x;
    int quad = t >> 1;
    int part = t & 1;
    int n0 = quad * 4;
    if (n0 >= N_NODES) return;

    unsigned long long acc[4][16];
#pragma unroll
    for (int p = 0; p < 16; p++) {
        unsigned long long b2 = pack_f32(sB[part * 32 + p * 2], sB[part * 32 + p * 2 + 1]);
#pragma unroll
        for (int n = 0; n < 4; n++) acc[n][p] = b2;
    }

    const float4* aB = (const float4*)(agg + (long)n0 * DIN);
    const float4* hB = (const float4*)(hin + (long)n0 * DIN);
    constexpr int R4 = DIN / 4;

    for (int k4 = 0; k4 < DIN / 4; k4++) {
        float4 av[4], hv[4];
#pragma unroll
        for (int n = 0; n < 4; n++) {
            av[n] = aB[(long)n * R4 + k4];
            hv[n] = hB[(long)n * R4 + k4];
        }
#pragma unroll
        for (int kk = 0; kk < 4; kk++) {
            int k = k4 * 4 + kk;
            const unsigned long long* wr =
                (const unsigned long long*)(sWrel + k * 64 + part * 32);
            const unsigned long long* wo =
                (const unsigned long long*)(sWroot + k * 64 + part * 32);
            unsigned long long ad[4], hd[4];
#pragma unroll
            for (int n = 0; n < 4; n++) {
                float as = (kk == 0) ? av[n].x : (kk == 1) ? av[n].y : (kk == 2) ? av[n].z : av[n].w;
                float hs = (kk == 0) ? hv[n].x : (kk == 1) ? hv[n].y : (kk == 2) ? hv[n].z : hv[n].w;
                ad[n] = dup_f32(as);
                hd[n] = dup_f32(hs);
            }
#pragma unroll
            for (int p = 0; p < 16; p++) {
                unsigned long long w1 = wr[p];
                unsigned long long w2 = wo[p];
#pragma unroll
                for (int n = 0; n < 4; n++) {
                    fma2(acc[n][p], w1, ad[n]);
                    fma2(acc[n][p], w2, hd[n]);
                }
            }
        }
    }

#pragma unroll
    for (int n = 0; n < 4; n++) {
        float4* d = (float4*)(hout + (long)(n0 + n) * 64 + part * 32);
#pragma unroll
        for (int j = 0; j < 16; j += 2) {
            float2 f0 = unpack_f32(acc[n][j]);
            float2 f1 = unpack_f32(acc[n][j + 1]);
            d[j / 2] = make_float4(fmaxf(f0.x, 0.f), fmaxf(f0.y, 0.f),
                                   fmaxf(f1.x, 0.f), fmaxf(f1.y, 0.f));
        }
    }
}

// ---------------- fused mean-pool + classifier ------------------------------
__global__ void __launch_bounds__(64)
pool_cls_kernel(const float* __restrict__ W_cls,
                const float* __restrict__ b_cls,
                float* __restrict__ out) {
    __shared__ float sp[64];
    int g = blockIdx.x;
    int lo = g_goff[g];
    int hi = g_goff[g + 1];
    int tid = threadIdx.x;

    float acc = 0.0f;
    int i = lo;
    for (; i + 4 <= hi; i += 4) {
        acc += g_h2[(long)(i + 0) * 64 + tid];
        acc += g_h2[(long)(i + 1) * 64 + tid];
        acc += g_h2[(long)(i + 2) * 64 + tid];
        acc += g_h2[(long)(i + 3) * 64 + tid];
    }
    for (; i < hi; i++) acc += g_h2[(long)i * 64 + tid];

    float cnt = fmaxf((float)(hi - lo), 1.0f);
    sp[tid] = acc / cnt;
    __syncthreads();

    if (tid < 10) {
        float r = b_cls[tid];
#pragma unroll
        for (int k = 0; k < 64; k++) r += sp[k] * W_cls[tid * 64 + k];
        out[(long)g * 10 + tid] = r;
    }
}

// ---------------- launch ----------------------------------------------------
extern "C" void kernel_launch(void* const* d_in, const int* in_sizes, int n_in,
                              void* d_out, int out_size) {
    const int* x     = (const int*)d_in[0];
    const int* edge  = (const int*)d_in[1];
    const int* batch = (const int*)d_in[2];

    int se = -1;
    for (int i = 3; i < n_in; i++) {
        if (in_sizes[i] == 128) { se = i; break; }
    }
    if (se < 0) se = (n_in == 16) ? 4 : 3;

    const float* shape_emb = (const float*)d_in[se + 0];
    const float* color_emb = (const float*)d_in[se + 1];
    const float* W_pre     = (const float*)d_in[se + 2];
    const float* b_pre     = (const float*)d_in[se + 3];
    const float* W_rel1    = (const float*)d_in[se + 4];
    const float* b_rel1    = (const float*)d_in[se + 5];
    const float* W_root1   = (const float*)d_in[se + 6];
    const float* W_rel2    = (const float*)d_in[se + 7];
    const float* b_rel2    = (const float*)d_in[se + 8];
    const float* W_root2   = (const float*)d_in[se + 9];
    const float* W_cls     = (const float*)d_in[se + 10];
    const float* b_cls     = (const float*)d_in[se + 11];

    float* out = (float*)d_out;

    void *p_agg1, *p_agg2, *p_h0, *p_h1, *p_h2, *p_zero;
    cudaGetSymbolAddress(&p_agg1, g_agg1);
    cudaGetSymbolAddress(&p_agg2, g_agg2);
    cudaGetSymbolAddress(&p_h0, g_h0);
    cudaGetSymbolAddress(&p_h1, g_h1);
    cudaGetSymbolAddress(&p_h2, g_h2);
    cudaGetSymbolAddress(&p_zero, g_zero);

    cudaMemsetAsync(p_zero, 0, (size_t)(N_NODES * 2 + N_GRAPHS) * sizeof(int));

    const int* src = edge;
    const int* dstp = edge + N_EDGES;

    hist_all_kernel<<<(N_EDGES + 255) / 256, 256>>>(dstp, batch);
    scanA_kernel<<<(N_CHUNKS * 32 + 255) / 256, 256>>>();
    scan2_kernel<<<2, 1024>>>();
    scanC_kernel<<<(N_CHUNKS * 32 + 255) / 256, 256>>>();

    scatter_embed_kernel<<<EMB_BLOCKS + SCAT_BLOCKS, 256>>>(
        src, dstp, x, shape_emb, color_emb, W_pre, b_pre);

    {
        int threads = N_NODES * 2;
        csr_agg_kernel<32, 1><<<(threads + 255) / 256, 256>>>(
            (const float*)p_h0, (float*)p_agg1);
    }
    {
        int threads = (N_NODES / 4) * 2;
        node_update_kernel<32><<<(threads + 127) / 128, 128>>>(
            (const float*)p_agg1, (const float*)p_h0, W_rel1, b_rel1, W_root1, (float*)p_h1);
    }
    {
        int threads = N_NODES * 4;
        csr_agg_kernel<64, 2><<<(threads + 255) / 256, 256>>>(
            (const float*)p_h1, (float*)p_agg2);
    }
    {
        int threads = (N_NODES / 4) * 2;
        node_update_kernel<64><<<(threads + 127) / 128, 128>>>(
            (const float*)p_agg2, (const float*)p_h1, W_rel2, b_rel2, W_root2, (float*)p_h2);
    }

    pool_cls_kernel<<<N_GRAPHS, 64>>>(W_cls, b_cls, out);

    (void)out_size;
}